// round 10
// baseline (speedup 1.0000x reference)
#include <cuda_runtime.h>
#include <cstdint>

// Soft quantizer forward on GB300 (Network_78872779423820).
// Forward value of soft_q + stop_grad(hard_q - soft_q) is exactly hard_q,
// i.e. nearest of 25 uniform levels in [-1, 1]:
//   k = clamp(rint((x + 1) * 12), 0, 24);  out = k * (2/24) - 1
// Pure HBM-bound elementwise map: 134 MB traffic -> ~17 us floor @ ~8 TB/s.
// Streaming (.cs) hints on both sides: zero reuse, working set > L2.

static __device__ __forceinline__ float quantize1(float x) {
    // scale = (L-1)/(Z_MAX-Z_MIN) = 24/2 = 12 ; step = 2/24 (same fp32 const as ref)
    float k = rintf(fmaf(x, 12.0f, 12.0f));
    k = fminf(fmaxf(k, 0.0f), 24.0f);
    return fmaf(k, 2.0f / 24.0f, -1.0f);
}

static __device__ __forceinline__ float4 quantize4(float4 v) {
    v.x = quantize1(v.x);
    v.y = quantize1(v.y);
    v.z = quantize1(v.z);
    v.w = quantize1(v.w);
    return v;
}

// Fast path: grid exactly covers n4, one float4 per thread, no loop.
__global__ __launch_bounds__(256)
void quant_kernel_exact(const float4* __restrict__ in, float4* __restrict__ out) {
    int i = blockIdx.x * blockDim.x + threadIdx.x;
    float4 v = __ldcs(&in[i]);      // streaming load (evict-first)
    __stcs(&out[i], quantize4(v));  // streaming store (no L2 allocate-retain)
}

// General path: grid-stride over float4s.
__global__ __launch_bounds__(256)
void quant_kernel_v4(const float4* __restrict__ in, float4* __restrict__ out, int n4) {
    int stride = gridDim.x * blockDim.x;
    for (int i = blockIdx.x * blockDim.x + threadIdx.x; i < n4; i += stride) {
        float4 v = __ldcs(&in[i]);
        __stcs(&out[i], quantize4(v));
    }
}

// Tail handler for element counts not divisible by 4 (not expected here, but safe).
__global__ __launch_bounds__(256)
void quant_kernel_tail(const float* __restrict__ in, float* __restrict__ out,
                       int start, int n) {
    int i = start + blockIdx.x * blockDim.x + threadIdx.x;
    if (i < n) out[i] = quantize1(in[i]);
}

extern "C" void kernel_launch(void* const* d_in, const int* in_sizes, int n_in,
                              void* d_out, int out_size) {
    const float* x = (const float*)d_in[0];
    float* y = (float*)d_out;
    int n = in_sizes[0];          // 4*64*256*256 = 16,777,216
    int n4 = n >> 2;

    const int threads = 256;
    if (n4 > 0) {
        if ((n4 % threads) == 0) {
            // Exact cover: 16384 blocks for the expected shape, 1 float4/thread.
            quant_kernel_exact<<<n4 / threads, threads>>>(
                (const float4*)x, (float4*)y);
        } else {
            int blocks = (n4 + threads - 1) / threads;
            if (blocks > 16384) blocks = 16384;
            quant_kernel_v4<<<blocks, threads>>>(
                (const float4*)x, (float4*)y, n4);
        }
    }
    int tail_start = n4 << 2;
    int tail = n - tail_start;
    if (tail > 0) {
        quant_kernel_tail<<<1, 256>>>(x, y, tail_start, n);
    }
}

// round 15
// speedup vs baseline: 1.2000x; 1.2000x over previous
#include <cuda_runtime.h>
#include <cstdint>

// Soft quantizer forward on GB300 (Network_78872779423820).
// Forward value == nearest of 25 uniform levels in [-1, 1].
// R10 ncu: DRAM=56.9%, kernel 19.0us, MLP_p1=1 starved the memory system.
// This round: 4 float4s per thread, loads front-batched (MLP_p1=4) to get
// ~24KB in-flight per SM (> ~17KB needed for 8TB/s at 577cyc latency).

static __device__ __forceinline__ float quantize1(float x) {
    float k = rintf(fmaf(x, 12.0f, 12.0f));
    k = fminf(fmaxf(k, 0.0f), 24.0f);
    return fmaf(k, 2.0f / 24.0f, -1.0f);
}

static __device__ __forceinline__ float4 quantize4(float4 v) {
    v.x = quantize1(v.x);
    v.y = quantize1(v.y);
    v.z = quantize1(v.z);
    v.w = quantize1(v.w);
    return v;
}

// Fast path: each thread handles 4 float4s at grid-stride offsets.
// Loads issued back-to-back (independent -> 4 outstanding LDG.128 per thread),
// then quantize + store. Grid exactly covers n4 = 4 * gridDim * blockDim.
__global__ __launch_bounds__(256)
void quant_kernel_x4(const float4* __restrict__ in, float4* __restrict__ out) {
    const int S = gridDim.x * blockDim.x;
    int i = blockIdx.x * blockDim.x + threadIdx.x;

    float4 a = __ldcs(&in[i]);
    float4 b = __ldcs(&in[i + S]);
    float4 c = __ldcs(&in[i + 2 * S]);
    float4 d = __ldcs(&in[i + 3 * S]);

    __stcs(&out[i],         quantize4(a));
    __stcs(&out[i + S],     quantize4(b));
    __stcs(&out[i + 2 * S], quantize4(c));
    __stcs(&out[i + 3 * S], quantize4(d));
}

// General path: grid-stride over float4s.
__global__ __launch_bounds__(256)
void quant_kernel_v4(const float4* __restrict__ in, float4* __restrict__ out, int n4) {
    int stride = gridDim.x * blockDim.x;
    for (int i = blockIdx.x * blockDim.x + threadIdx.x; i < n4; i += stride) {
        float4 v = __ldcs(&in[i]);
        __stcs(&out[i], quantize4(v));
    }
}

// Tail handler for element counts not divisible by 4.
__global__ __launch_bounds__(256)
void quant_kernel_tail(const float* __restrict__ in, float* __restrict__ out,
                       int start, int n) {
    int i = start + blockIdx.x * blockDim.x + threadIdx.x;
    if (i < n) out[i] = quantize1(in[i]);
}

extern "C" void kernel_launch(void* const* d_in, const int* in_sizes, int n_in,
                              void* d_out, int out_size) {
    const float* x = (const float*)d_in[0];
    float* y = (float*)d_out;
    int n = in_sizes[0];          // 4*64*256*256 = 16,777,216
    int n4 = n >> 2;

    const int threads = 256;
    const int per_block = threads * 4;     // float4s per block in x4 kernel
    if (n4 > 0) {
        if ((n4 % per_block) == 0) {
            // Expected shape: n4 = 4,194,304 -> 4096 blocks, 4 float4s/thread.
            quant_kernel_x4<<<n4 / per_block, threads>>>(
                (const float4*)x, (float4*)y);
        } else {
            int blocks = (n4 + threads - 1) / threads;
            if (blocks > 16384) blocks = 16384;
            quant_kernel_v4<<<blocks, threads>>>(
                (const float4*)x, (float4*)y, n4);
        }
    }
    int tail_start = n4 << 2;
    int tail = n - tail_start;
    if (tail > 0) {
        quant_kernel_tail<<<1, 256>>>(x, y, tail_start, n);
    }
}